// round 14
// baseline (speedup 1.0000x reference)
#include <cuda_runtime.h>
#include <cuda_fp16.h>
#include <mma.h>

using namespace nvcuda;

// Problem constants (fixed by the dataset)
constexpr int NN = 100000;   // nodes
constexpr int EE = 1600000;  // edges
constexpr int DD = 64;       // feature dim
constexpr int GG = 512;      // graphs
constexpr int CC = 10;       // classes
constexpr int LL = 5;        // layers (4 conv layers)
constexpr float BN_EPS = 1e-5f;
constexpr int SCAN_B = 1024;
constexpr int NBLK = (NN + SCAN_B - 1) / SCAN_B;   // 98

// Scratch (device globals; no allocation allowed)
__device__ __align__(16) __half g_u16[NN * DD];   // layer activations (transformed in place)
__device__ __align__(16) __half g_t16[NN * DD];   // GEMM1 output (fp16)
__device__ float g_pooled[LL * GG * DD];
__device__ float g_stats[8 * 128];                // per BN: [0..63]=sum, [64..127]=sumsq
__device__ int   g_rowptr[NN + 1];
__device__ int   g_cursor[NN];
__device__ int   g_csr[EE];
__device__ int   g_bsum[NBLK];

// ---------------------------------------------------------------------------
// helpers
// ---------------------------------------------------------------------------
__device__ __forceinline__ void red4(float* p, float4 v) {
    asm volatile("red.global.add.v4.f32 [%0], {%1,%2,%3,%4};"
                 :: "l"(p), "f"(v.x), "f"(v.y), "f"(v.z), "f"(v.w) : "memory");
}

__device__ __forceinline__ float4 ldh4(const __half* p) {
    uint2 r = *(const uint2*)p;
    __half2 a = *(__half2*)&r.x;
    __half2 b = *(__half2*)&r.y;
    float2 fa = __half22float2(a), fb = __half22float2(b);
    return make_float4(fa.x, fa.y, fb.x, fb.y);
}

__device__ __forceinline__ void sth4(__half* p, float4 v) {
    uint2 r;
    *(__half2*)&r.x = __floats2half2_rn(v.x, v.y);
    *(__half2*)&r.y = __floats2half2_rn(v.z, v.w);
    *(uint2*)p = r;
}

__device__ __forceinline__ float4 bnrelu4(float4 v, float a0, float a1, float a2, float a3,
                                          float b0, float b1, float b2, float b3) {
    v.x = fmaxf(fmaf(a0, v.x, b0), 0.f);
    v.y = fmaxf(fmaf(a1, v.y, b1), 0.f);
    v.z = fmaxf(fmaf(a2, v.z, b2), 0.f);
    v.w = fmaxf(fmaf(a3, v.w, b3), 0.f);
    return v;
}

// accumulate 8 halves (uint4) into 8 fp32 accumulators
__device__ __forceinline__ void acc8(float* a, uint4 r) {
    float2 f0 = __half22float2(*(__half2*)&r.x);
    float2 f1 = __half22float2(*(__half2*)&r.y);
    float2 f2 = __half22float2(*(__half2*)&r.z);
    float2 f3 = __half22float2(*(__half2*)&r.w);
    a[0] += f0.x; a[1] += f0.y; a[2] += f1.x; a[3] += f1.y;
    a[4] += f2.x; a[5] += f2.y; a[6] += f3.x; a[7] += f3.y;
}

// tree-accumulate 4 rows (fp16 pairwise, then fp32): a += (r0+r1)+(r2+r3)
__device__ __forceinline__ void acc8x4tree(float* a, uint4 r0, uint4 r1,
                                           uint4 r2, uint4 r3) {
    __half2 t0 = __hadd2(__hadd2(*(__half2*)&r0.x, *(__half2*)&r1.x),
                         __hadd2(*(__half2*)&r2.x, *(__half2*)&r3.x));
    __half2 t1 = __hadd2(__hadd2(*(__half2*)&r0.y, *(__half2*)&r1.y),
                         __hadd2(*(__half2*)&r2.y, *(__half2*)&r3.y));
    __half2 t2 = __hadd2(__hadd2(*(__half2*)&r0.z, *(__half2*)&r1.z),
                         __hadd2(*(__half2*)&r2.z, *(__half2*)&r3.z));
    __half2 t3 = __hadd2(__hadd2(*(__half2*)&r0.w, *(__half2*)&r1.w),
                         __hadd2(*(__half2*)&r2.w, *(__half2*)&r3.w));
    float2 f0 = __half22float2(t0);
    float2 f1 = __half22float2(t1);
    float2 f2 = __half22float2(t2);
    float2 f3 = __half22float2(t3);
    a[0] += f0.x; a[1] += f0.y; a[2] += f1.x; a[3] += f1.y;
    a[4] += f2.x; a[5] += f2.y; a[6] += f3.x; a[7] += f3.y;
}

// ---------------------------------------------------------------------------
// zero accumulators + degree counters (reuse g_rowptr as count buffer)
// ---------------------------------------------------------------------------
__global__ void zerok(float* __restrict__ pooled, float* __restrict__ stats,
                      int* __restrict__ cnt) {
    int i = blockIdx.x * 256 + threadIdx.x;
    if (i < LL * GG * DD) pooled[i] = 0.f;
    if (i < 8 * 128) stats[i] = 0.f;
    if (i <= NN) cnt[i] = 0;
}

// ---------------------------------------------------------------------------
// CSR build (int4-vectorized edge reads)
// ---------------------------------------------------------------------------
__global__ void __launch_bounds__(256) hist_kernel(const int* __restrict__ ei,
                                                   int* __restrict__ cnt) {
    int e4 = blockIdx.x * 256 + threadIdx.x;
    if (e4 < EE / 4) {
        int4 d = ((const int4*)(ei + EE))[e4];
        atomicAdd(&cnt[d.x], 1);
        atomicAdd(&cnt[d.y], 1);
        atomicAdd(&cnt[d.z], 1);
        atomicAdd(&cnt[d.w], 1);
    }
}

__global__ void __launch_bounds__(SCAN_B) scanA_kernel(int* __restrict__ rp,
                                                       int* __restrict__ bsum) {
    __shared__ int sm[SCAN_B];
    int gid = blockIdx.x * SCAN_B + threadIdx.x;
    int v = (gid < NN) ? rp[gid] : 0;
    sm[threadIdx.x] = v;
    __syncthreads();
    for (int off = 1; off < SCAN_B; off <<= 1) {
        int t = (threadIdx.x >= off) ? sm[threadIdx.x - off] : 0;
        __syncthreads();
        sm[threadIdx.x] += t;
        __syncthreads();
    }
    if (gid < NN) rp[gid] = sm[threadIdx.x] - v;   // exclusive
    if (threadIdx.x == SCAN_B - 1) bsum[blockIdx.x] = sm[SCAN_B - 1];
}

__global__ void __launch_bounds__(SCAN_B) scanC_kernel(int* __restrict__ rp,
                                                       const int* __restrict__ bsum,
                                                       int* __restrict__ cursor) {
    __shared__ int sb[128];
    int tid = threadIdx.x;
    if (tid < 128) sb[tid] = (tid < (int)blockIdx.x && tid < NBLK) ? bsum[tid] : 0;
    __syncthreads();
#pragma unroll
    for (int s = 64; s > 0; s >>= 1) {
        if (tid < s) sb[tid] += sb[tid + s];
        __syncthreads();
    }
    int off = sb[0];
    int gid = blockIdx.x * SCAN_B + tid;
    if (gid < NN) {
        int v = rp[gid] + off;
        rp[gid] = v;
        cursor[gid] = v;
    }
    if (gid == 0) rp[NN] = EE;
}

__global__ void __launch_bounds__(256) fill_kernel(const int* __restrict__ ei,
                                                   int* __restrict__ cursor,
                                                   int* __restrict__ csr) {
    int e4 = blockIdx.x * 256 + threadIdx.x;
    if (e4 < EE / 4) {
        int4 s = ((const int4*)ei)[e4];
        int4 d = ((const int4*)(ei + EE))[e4];
        int p0 = atomicAdd(&cursor[d.x], 1); csr[p0] = s.x;
        int p1 = atomicAdd(&cursor[d.y], 1); csr[p1] = s.y;
        int p2 = atomicAdd(&cursor[d.z], 1); csr[p2] = s.z;
        int p3 = atomicAdd(&cursor[d.w], 1); csr[p3] = s.w;
    }
}

// ---------------------------------------------------------------------------
// convert x (fp32) -> u16 (fp16); pool exact x into pooled[0]
// ---------------------------------------------------------------------------
__global__ void __launch_bounds__(256) conv_kernel(
    const float* __restrict__ x, const int* __restrict__ batch,
    __half* __restrict__ u16, float* __restrict__ pooled0)
{
    int idx = blockIdx.x * 256 + threadIdx.x;
    int n = idx >> 4;
    int j = (idx & 15) << 2;
    float4 v = *(const float4*)(x + n * DD + j);
    sth4(u16 + n * DD + j, v);
    red4(pooled0 + batch[n] * DD + j, v);
}

// ---------------------------------------------------------------------------
// FUSED gather + GEMM1:  t16 = (gather(v16)) @ W1 + b1, fused column stats.
// Warp-local pipeline: each warp gathers its own 16 rows into its Ah slice
// (8 thr/node, 4 passes; fp16 pairwise trees into fp32), __syncwarp, wmma,
// then epilogue through its own Ah slice reused as float scratch (2 passes
// of 16x32). Only block-wide syncs: W-load barrier + final stats write.
// ---------------------------------------------------------------------------
struct G1Smem {
    __half Wh[64 * 72];      // 9216 B
    __half Ah[128 * 72];     // 18432 B; per-warp 16x72 slice doubles as epilogue scratch
    float  sst[128];         // 512 B
};

__global__ void __launch_bounds__(256) gin1_kernel(
    const __half* __restrict__ v16,
    const int* __restrict__ rowptr, const int* __restrict__ csr,
    const float* __restrict__ eps_l,
    const float* __restrict__ Wf, const float* __restrict__ bias,
    __half* __restrict__ OutH, float* __restrict__ st_out, int nrows)
{
    __shared__ G1Smem sm;
    const int tid = threadIdx.x;
    const int w = tid >> 5;
    const int lane = tid & 31;
    const int row0 = blockIdx.x * 128;

    if (tid < 128) sm.sst[tid] = 0.f;
    // W (fp32 global) -> fp16 smem, stride 72
    for (int i = tid; i < 1024; i += 256) {
        int k = i >> 4, c = (i & 15) << 2;
        float4 wv = *(const float4*)(Wf + k * 64 + c);
        uint2 p;
        *(__half2*)&p.x = __floats2half2_rn(wv.x, wv.y);
        *(__half2*)&p.y = __floats2half2_rn(wv.z, wv.w);
        *(uint2*)&sm.Wh[k * 72 + c] = p;
    }
    __syncthreads();

    // -------- warp-local gather of 16 rows into Ah slice --------
    const float em1 = 1.0f + *eps_l;
    const int j = (lane & 7) << 3;   // half offset within row

#pragma unroll 1
    for (int p = 0; p < 4; p++) {
        int r = w * 16 + p * 4 + (lane >> 3);
        int n = row0 + r;
        float a[8] = {0.f, 0.f, 0.f, 0.f, 0.f, 0.f, 0.f, 0.f};
        if (n < nrows) {
            {
                uint4 rr = *(const uint4*)(v16 + n * DD + j);
                float2 f0 = __half22float2(*(__half2*)&rr.x);
                float2 f1 = __half22float2(*(__half2*)&rr.y);
                float2 f2 = __half22float2(*(__half2*)&rr.z);
                float2 f3 = __half22float2(*(__half2*)&rr.w);
                a[0] = em1 * f0.x; a[1] = em1 * f0.y; a[2] = em1 * f1.x; a[3] = em1 * f1.y;
                a[4] = em1 * f2.x; a[5] = em1 * f2.y; a[6] = em1 * f3.x; a[7] = em1 * f3.y;
            }
            int s = rowptr[n], e = rowptr[n + 1];
            int i = s;
            for (; i + 4 <= e; i += 4) {
                int s0 = csr[i], s1 = csr[i + 1], s2 = csr[i + 2], s3 = csr[i + 3];
                uint4 r0 = *(const uint4*)(v16 + s0 * DD + j);
                uint4 r1 = *(const uint4*)(v16 + s1 * DD + j);
                uint4 r2 = *(const uint4*)(v16 + s2 * DD + j);
                uint4 r3 = *(const uint4*)(v16 + s3 * DD + j);
                acc8x4tree(a, r0, r1, r2, r3);
            }
            for (; i < e; i++) {
                uint4 rr = *(const uint4*)(v16 + csr[i] * DD + j);
                acc8(a, rr);
            }
        }
        uint4 o;
        *(__half2*)&o.x = __floats2half2_rn(a[0], a[1]);
        *(__half2*)&o.y = __floats2half2_rn(a[2], a[3]);
        *(__half2*)&o.z = __floats2half2_rn(a[4], a[5]);
        *(__half2*)&o.w = __floats2half2_rn(a[6], a[7]);
        *(uint4*)&sm.Ah[r * 72 + j] = o;
    }
    __syncwarp();

    // -------- warp-local tensor-core GEMM on its 16 rows --------
    wmma::fragment<wmma::accumulator, 16, 16, 16, float> cf[4];
#pragma unroll
    for (int n = 0; n < 4; n++) wmma::fill_fragment(cf[n], 0.f);

#pragma unroll
    for (int k = 0; k < 4; k++) {
        wmma::fragment<wmma::matrix_a, 16, 16, 16, __half, wmma::row_major> af;
        wmma::load_matrix_sync(af, &sm.Ah[(w * 16) * 72 + k * 16], 72);
#pragma unroll
        for (int n = 0; n < 4; n++) {
            wmma::fragment<wmma::matrix_b, 16, 16, 16, __half, wmma::row_major> bf;
            wmma::load_matrix_sync(bf, &sm.Wh[(k * 16) * 72 + n * 16], 72);
            wmma::mma_sync(cf[n], af, bf, cf[n]);
        }
    }

    // -------- warp-local epilogue via own Ah slice as float scratch --------
    float* ep = (float*)&sm.Ah[(w * 16) * 72];   // 2304 B slice; use 16x32 f32 = 2048 B
#pragma unroll 1
    for (int h = 0; h < 2; h++) {
        __syncwarp();
        wmma::store_matrix_sync(ep,      cf[2 * h + 0], 32, wmma::mem_row_major);
        wmma::store_matrix_sync(ep + 16, cf[2 * h + 1], 32, wmma::mem_row_major);
        __syncwarp();
        const int c4 = (lane & 7) << 2;     // 0..28 within this 32-col half
        const int cg = h * 32 + c4;         // global column base
        float4 b4 = *(const float4*)(bias + cg);
        float4 s4 = make_float4(0.f, 0.f, 0.f, 0.f), q4 = s4;
#pragma unroll
        for (int rr2 = 0; rr2 < 4; rr2++) {
            int r = (lane >> 3) + 4 * rr2;  // 0..15
            int gr = row0 + w * 16 + r;
            if (gr < nrows) {
                float4 v = *(const float4*)(ep + r * 32 + c4);
                v.x += b4.x; v.y += b4.y; v.z += b4.z; v.w += b4.w;
                sth4(OutH + gr * 64 + cg, v);
                s4.x += v.x; s4.y += v.y; s4.z += v.z; s4.w += v.w;
                q4.x += v.x * v.x; q4.y += v.y * v.y; q4.z += v.z * v.z; q4.w += v.w * v.w;
            }
        }
        // lanes sharing c4 differ in bits 3,4
#pragma unroll
        for (int m = 8; m <= 16; m <<= 1) {
            s4.x += __shfl_xor_sync(~0u, s4.x, m); s4.y += __shfl_xor_sync(~0u, s4.y, m);
            s4.z += __shfl_xor_sync(~0u, s4.z, m); s4.w += __shfl_xor_sync(~0u, s4.w, m);
            q4.x += __shfl_xor_sync(~0u, q4.x, m); q4.y += __shfl_xor_sync(~0u, q4.y, m);
            q4.z += __shfl_xor_sync(~0u, q4.z, m); q4.w += __shfl_xor_sync(~0u, q4.w, m);
        }
        if (lane < 8) {
            atomicAdd(&sm.sst[cg + 0], s4.x); atomicAdd(&sm.sst[cg + 1], s4.y);
            atomicAdd(&sm.sst[cg + 2], s4.z); atomicAdd(&sm.sst[cg + 3], s4.w);
            atomicAdd(&sm.sst[64 + cg + 0], q4.x); atomicAdd(&sm.sst[64 + cg + 1], q4.y);
            atomicAdd(&sm.sst[64 + cg + 2], q4.z); atomicAdd(&sm.sst[64 + cg + 3], q4.w);
        }
    }
    __syncthreads();
    if (tid < 128) atomicAdd(&st_out[tid], sm.sst[tid]);
}

// ---------------------------------------------------------------------------
// bnapply: u16 = relu(bn(u16)) in place (once per node) + pool into pooled_l
// ---------------------------------------------------------------------------
__global__ void __launch_bounds__(256) bnapply_kernel(
    __half* __restrict__ u16, const float* __restrict__ st,
    const float* __restrict__ gamma, const float* __restrict__ beta,
    const int* __restrict__ batch, float* __restrict__ pooled_l)
{
    __shared__ float ab_s[128];
    const int tid = threadIdx.x;
    if (tid < 64) {
        const float inv_n = 1.0f / (float)NN;
        float m = st[tid] * inv_n;
        float v = st[64 + tid] * inv_n - m * m;
        float rs = rsqrtf(v + BN_EPS);
        float al = gamma[tid] * rs;
        ab_s[tid] = al;
        ab_s[64 + tid] = beta[tid] - al * m;
    }
    __syncthreads();
    int idx = blockIdx.x * 256 + tid;
    int n = idx >> 4;
    int j = (idx & 15) << 2;
    float4 v = ldh4(u16 + n * DD + j);
    v = bnrelu4(v, ab_s[j + 0], ab_s[j + 1], ab_s[j + 2], ab_s[j + 3],
                ab_s[64 + j + 0], ab_s[64 + j + 1], ab_s[64 + j + 2], ab_s[64 + j + 3]);
    sth4(u16 + n * DD + j, v);
    red4(pooled_l + batch[n] * DD + j, v);
}

// ---------------------------------------------------------------------------
// GEMM2 (unchanged): u16 = relu(bn(t16)) @ W2 + b2 (fp16 out), fused stats.
// ---------------------------------------------------------------------------
struct GemmSmem {
    __half Wh[64 * 72];
    union {
        __half Ah[128 * 72];
        float  Ep[8 * 16 * 64];
    } u;
    float ab[128];
    float sst[128];
};

__global__ void __launch_bounds__(256) gemmh_kernel(
    const __half* __restrict__ A16, const float* __restrict__ Wf,
    const float* __restrict__ bias,
    const float* __restrict__ st_in, const float* __restrict__ gamma,
    const float* __restrict__ beta,
    __half* __restrict__ OutH, float* __restrict__ st_out, int nrows)
{
    __shared__ GemmSmem sm;
    const int tid = threadIdx.x;
    const int row0 = blockIdx.x * 128;

    if (tid < 128) sm.sst[tid] = 0.f;
    if (tid < 64) {
        const float inv_n = 1.0f / (float)NN;
        float m = st_in[tid] * inv_n;
        float v = st_in[64 + tid] * inv_n - m * m;
        float rs = rsqrtf(v + BN_EPS);
        float al = gamma[tid] * rs;
        sm.ab[tid] = al;
        sm.ab[64 + tid] = beta[tid] - al * m;
    }
    for (int i = tid; i < 1024; i += 256) {
        int k = i >> 4, c = (i & 15) << 2;
        float4 wv = *(const float4*)(Wf + k * 64 + c);
        uint2 p;
        *(__half2*)&p.x = __floats2half2_rn(wv.x, wv.y);
        *(__half2*)&p.y = __floats2half2_rn(wv.z, wv.w);
        *(uint2*)&sm.Wh[k * 72 + c] = p;
    }
    __syncthreads();

    for (int i = tid; i < 2048; i += 256) {
        int r = i >> 4, c = (i & 15) << 2;
        int gr = row0 + r;
        float4 a = make_float4(0.f, 0.f, 0.f, 0.f);
        if (gr < nrows) {
            a = ldh4(A16 + gr * 64 + c);
            a = bnrelu4(a, sm.ab[c + 0], sm.ab[c + 1], sm.ab[c + 2], sm.ab[c + 3],
                        sm.ab[64 + c + 0], sm.ab[64 + c + 1],
                        sm.ab[64 + c + 2], sm.ab[64 + c + 3]);
        }
        sth4(&sm.u.Ah[r * 72 + c], a);
    }
    __syncthreads();

    const int w = tid >> 5;
    const int lane = tid & 31;

    wmma::fragment<wmma::accumulator, 16, 16, 16, float> cf[4];
#pragma unroll
    for (int n = 0; n < 4; n++) wmma::fill_fragment(cf[n], 0.f);

#pragma unroll
    for (int k = 0; k < 4; k++) {
        wmma::fragment<wmma::matrix_a, 16, 16, 16, __half, wmma::row_major> af;
        wmma::load_matrix_sync(af, &sm.u.Ah[(w * 16) * 72 + k * 16], 72);
#pragma unroll
        for (int n = 0; n < 4; n++) {
            wmma::fragment<wmma::matrix_b, 16, 16, 16, __half, wmma::row_major> bf;
            wmma::load_matrix_sync(bf, &sm.Wh[(k * 16) * 72 + n * 16], 72);
            wmma::mma_sync(cf[n], af, bf, cf[n]);
        }
    }
    __syncthreads();   // Ah no longer needed; Ep aliases it

    float* ep = sm.u.Ep + w * 1024;
#pragma unroll
    for (int n = 0; n < 4; n++)
        wmma::store_matrix_sync(ep + n * 16, cf[n], 64, wmma::mem_row_major);
    __syncwarp();

    const int c4 = (lane & 15) << 2;
    float4 b4 = *(const float4*)(bias + c4);
    float4 s = make_float4(0.f, 0.f, 0.f, 0.f), q = s;
#pragma unroll
    for (int jj = 0; jj < 8; jj++) {
        int r = (lane >> 4) + 2 * jj;
        int gr = row0 + w * 16 + r;
        if (gr < nrows) {
            float4 v = *(const float4*)(ep + r * 64 + c4);
            v.x += b4.x; v.y += b4.y; v.z += b4.z; v.w += b4.w;
            sth4(OutH + gr * 64 + c4, v);
            s.x += v.x; s.y += v.y; s.z += v.z; s.w += v.w;
            q.x += v.x * v.x; q.y += v.y * v.y; q.z += v.z * v.z; q.w += v.w * v.w;
        }
    }
    s.x += __shfl_xor_sync(~0u, s.x, 16); s.y += __shfl_xor_sync(~0u, s.y, 16);
    s.z += __shfl_xor_sync(~0u, s.z, 16); s.w += __shfl_xor_sync(~0u, s.w, 16);
    q.x += __shfl_xor_sync(~0u, q.x, 16); q.y += __shfl_xor_sync(~0u, q.y, 16);
    q.z += __shfl_xor_sync(~0u, q.z, 16); q.w += __shfl_xor_sync(~0u, q.w, 16);
    if (lane < 16) {
        atomicAdd(&sm.sst[c4 + 0], s.x); atomicAdd(&sm.sst[c4 + 1], s.y);
        atomicAdd(&sm.sst[c4 + 2], s.z); atomicAdd(&sm.sst[c4 + 3], s.w);
        atomicAdd(&sm.sst[64 + c4 + 0], q.x); atomicAdd(&sm.sst[64 + c4 + 1], q.y);
        atomicAdd(&sm.sst[64 + c4 + 2], q.z); atomicAdd(&sm.sst[64 + c4 + 3], q.w);
    }
    __syncthreads();
    if (tid < 128) atomicAdd(&st_out[tid], sm.sst[tid]);
}

// ---------------------------------------------------------------------------
// final readout
// ---------------------------------------------------------------------------
__global__ void score_kernel(const float* __restrict__ pooled,
                             const float* __restrict__ Wp,
                             const float* __restrict__ bp,
                             float* __restrict__ out)
{
    int t = blockIdx.x * 256 + threadIdx.x;
    if (t >= GG * CC) return;
    int g = t / CC, c = t % CC;
    float acc = 0.f;
#pragma unroll
    for (int l = 0; l < LL; l++) {
        acc += bp[l * CC + c];
        const float* pl = pooled + (l * GG + g) * DD;
        const float* wl = Wp + l * DD * CC + c;
        float s = 0.f;
#pragma unroll
        for (int d = 0; d < DD; d++) s += pl[d] * wl[d * CC];
        acc += s;
    }
    out[g * CC + c] = acc;
}

// ---------------------------------------------------------------------------
extern "C" void kernel_launch(void* const* d_in, const int* in_sizes, int n_in,
                              void* d_out, int out_size)
{
    (void)in_sizes; (void)n_in; (void)out_size;
    const float* x     = (const float*)d_in[0];
    const int*   ei    = (const int*)d_in[1];
    const int*   batch = (const int*)d_in[2];
    const float* eps   = (const float*)d_in[3];
    const float* W1    = (const float*)d_in[4];
    const float* b1    = (const float*)d_in[5];
    const float* g1    = (const float*)d_in[6];
    const float* be1   = (const float*)d_in[7];
    const float* W2    = (const float*)d_in[8];
    const float* b2    = (const float*)d_in[9];
    const float* gout  = (const float*)d_in[10];
    const float* beout = (const float*)d_in[11];
    const float* Wp    = (const float*)d_in[12];
    const float* bp    = (const float*)d_in[13];

    __half *u16, *t16;
    float *pooled, *stats;
    int *rowptr, *cursor, *csr, *bsum;
    cudaGetSymbolAddress((void**)&u16, g_u16);
    cudaGetSymbolAddress((void**)&t16, g_t16);
    cudaGetSymbolAddress((void**)&pooled, g_pooled);
    cudaGetSymbolAddress((void**)&stats, g_stats);
    cudaGetSymbolAddress((void**)&rowptr, g_rowptr);
    cudaGetSymbolAddress((void**)&cursor, g_cursor);
    cudaGetSymbolAddress((void**)&csr, g_csr);
    cudaGetSymbolAddress((void**)&bsum, g_bsum);

    const int HPB  = (NN * 16) / 256;         // 6250 (exact, 16 thr/node kernels)
    const int EB4  = (EE / 4 + 255) / 256;    // 1563 (int4 edge kernels)
    const int GMB  = (NN + 127) / 128;        // 782

    zerok<<<(LL * GG * DD + 255) / 256, 256>>>(pooled, stats, rowptr);

    // CSR build
    hist_kernel<<<EB4, 256>>>(ei, rowptr);
    scanA_kernel<<<NBLK, SCAN_B>>>(rowptr, bsum);
    scanC_kernel<<<NBLK, SCAN_B>>>(rowptr, bsum, cursor);
    fill_kernel<<<EB4, 256>>>(ei, cursor, csr);

    // x -> fp16 (identity "transform"), pool hidden_rep[0] exactly
    conv_kernel<<<HPB, 256>>>(x, batch, u16, pooled);

    for (int l = 0; l < LL - 1; l++) {
        // fused gather + GEMM1: t16 = gather(u16) @ W1 + b1, stats -> 2l
        gin1_kernel<<<GMB, 256>>>(u16, rowptr, csr, eps + l,
                                  W1 + l * 4096, b1 + l * 64,
                                  t16, stats + (2 * l) * 128, NN);
        // GEMM2: u16 = relu(bn(t16)) @ W2 + b2, stats -> 2l+1
        gemmh_kernel<<<GMB, 256>>>(t16, W2 + l * 4096, b2 + l * 64,
                                   stats + (2 * l) * 128, g1 + l * 64, be1 + l * 64,
                                   u16, stats + (2 * l + 1) * 128, NN);
        // h_{l+1} = relu(bn(u16)) in place + pool hidden_rep[l+1]
        bnapply_kernel<<<HPB, 256>>>(u16, stats + (2 * l + 1) * 128,
                                     gout + l * 64, beout + l * 64,
                                     batch, pooled + (l + 1) * GG * DD);
    }

    score_kernel<<<(GG * CC + 255) / 256, 256>>>(pooled, Wp, bp, (float*)d_out);
}

// round 16
// speedup vs baseline: 1.1286x; 1.1286x over previous
#include <cuda_runtime.h>
#include <cuda_fp16.h>
#include <mma.h>

using namespace nvcuda;

// Problem constants (fixed by the dataset)
constexpr int NN = 100000;   // nodes
constexpr int EE = 1600000;  // edges
constexpr int DD = 64;       // feature dim
constexpr int GG = 512;      // graphs
constexpr int CC = 10;       // classes
constexpr int LL = 5;        // layers (4 conv layers)
constexpr float BN_EPS = 1e-5f;
constexpr int SCAN_B = 1024;
constexpr int NBLK = (NN + SCAN_B - 1) / SCAN_B;   // 98

// Scratch (device globals; no allocation allowed)
__device__ __align__(16) __half g_u16[NN * DD];   // layer activations (transformed in place)
__device__ __align__(16) __half g_z16[NN * DD];   // aggregated features (fp16)
__device__ __align__(16) __half g_t16[NN * DD];   // GEMM1 output (fp16)
__device__ float g_pooled[LL * GG * DD];
__device__ float g_stats[8 * 128];                // per BN: [0..63]=sum, [64..127]=sumsq
__device__ int   g_rowptr[NN + 1];
__device__ int   g_cursor[NN];
__device__ int   g_csr[EE];                       // stores src*DD (pre-scaled offsets)
__device__ int   g_bsum[NBLK];

// ---------------------------------------------------------------------------
// helpers
// ---------------------------------------------------------------------------
__device__ __forceinline__ void red4(float* p, float4 v) {
    asm volatile("red.global.add.v4.f32 [%0], {%1,%2,%3,%4};"
                 :: "l"(p), "f"(v.x), "f"(v.y), "f"(v.z), "f"(v.w) : "memory");
}

__device__ __forceinline__ float4 ldh4(const __half* p) {
    uint2 r = *(const uint2*)p;
    __half2 a = *(__half2*)&r.x;
    __half2 b = *(__half2*)&r.y;
    float2 fa = __half22float2(a), fb = __half22float2(b);
    return make_float4(fa.x, fa.y, fb.x, fb.y);
}

__device__ __forceinline__ void sth4(__half* p, float4 v) {
    uint2 r;
    *(__half2*)&r.x = __floats2half2_rn(v.x, v.y);
    *(__half2*)&r.y = __floats2half2_rn(v.z, v.w);
    *(uint2*)p = r;
}

__device__ __forceinline__ float4 bnrelu4(float4 v, float a0, float a1, float a2, float a3,
                                          float b0, float b1, float b2, float b3) {
    v.x = fmaxf(fmaf(a0, v.x, b0), 0.f);
    v.y = fmaxf(fmaf(a1, v.y, b1), 0.f);
    v.z = fmaxf(fmaf(a2, v.z, b2), 0.f);
    v.w = fmaxf(fmaf(a3, v.w, b3), 0.f);
    return v;
}

// accumulate 8 halves (uint4) into 8 fp32 accumulators
__device__ __forceinline__ void acc8(float* a, uint4 r) {
    float2 f0 = __half22float2(*(__half2*)&r.x);
    float2 f1 = __half22float2(*(__half2*)&r.y);
    float2 f2 = __half22float2(*(__half2*)&r.z);
    float2 f3 = __half22float2(*(__half2*)&r.w);
    a[0] += f0.x; a[1] += f0.y; a[2] += f1.x; a[3] += f1.y;
    a[4] += f2.x; a[5] += f2.y; a[6] += f3.x; a[7] += f3.y;
}

// tree-accumulate 4 rows (fp16 pairwise, then fp32): a += (r0+r1)+(r2+r3)
__device__ __forceinline__ void acc8x4tree(float* a, uint4 r0, uint4 r1,
                                           uint4 r2, uint4 r3) {
    __half2 t0 = __hadd2(__hadd2(*(__half2*)&r0.x, *(__half2*)&r1.x),
                         __hadd2(*(__half2*)&r2.x, *(__half2*)&r3.x));
    __half2 t1 = __hadd2(__hadd2(*(__half2*)&r0.y, *(__half2*)&r1.y),
                         __hadd2(*(__half2*)&r2.y, *(__half2*)&r3.y));
    __half2 t2 = __hadd2(__hadd2(*(__half2*)&r0.z, *(__half2*)&r1.z),
                         __hadd2(*(__half2*)&r2.z, *(__half2*)&r3.z));
    __half2 t3 = __hadd2(__hadd2(*(__half2*)&r0.w, *(__half2*)&r1.w),
                         __hadd2(*(__half2*)&r2.w, *(__half2*)&r3.w));
    float2 f0 = __half22float2(t0);
    float2 f1 = __half22float2(t1);
    float2 f2 = __half22float2(t2);
    float2 f3 = __half22float2(t3);
    a[0] += f0.x; a[1] += f0.y; a[2] += f1.x; a[3] += f1.y;
    a[4] += f2.x; a[5] += f2.y; a[6] += f3.x; a[7] += f3.y;
}

// ---------------------------------------------------------------------------
// zero accumulators + degree counters (reuse g_rowptr as count buffer)
// ---------------------------------------------------------------------------
__global__ void zerok(float* __restrict__ pooled, float* __restrict__ stats,
                      int* __restrict__ cnt) {
    int i = blockIdx.x * 256 + threadIdx.x;
    if (i < LL * GG * DD) pooled[i] = 0.f;
    if (i < 8 * 128) stats[i] = 0.f;
    if (i <= NN) cnt[i] = 0;
}

// ---------------------------------------------------------------------------
// CSR build (int4-vectorized edge reads; csr stores src*DD)
// ---------------------------------------------------------------------------
__global__ void __launch_bounds__(256) hist_kernel(const int* __restrict__ ei,
                                                   int* __restrict__ cnt) {
    int e4 = blockIdx.x * 256 + threadIdx.x;
    if (e4 < EE / 4) {
        int4 d = ((const int4*)(ei + EE))[e4];
        atomicAdd(&cnt[d.x], 1);
        atomicAdd(&cnt[d.y], 1);
        atomicAdd(&cnt[d.z], 1);
        atomicAdd(&cnt[d.w], 1);
    }
}

__global__ void __launch_bounds__(SCAN_B) scanA_kernel(int* __restrict__ rp,
                                                       int* __restrict__ bsum) {
    __shared__ int sm[SCAN_B];
    int gid = blockIdx.x * SCAN_B + threadIdx.x;
    int v = (gid < NN) ? rp[gid] : 0;
    sm[threadIdx.x] = v;
    __syncthreads();
    for (int off = 1; off < SCAN_B; off <<= 1) {
        int t = (threadIdx.x >= off) ? sm[threadIdx.x - off] : 0;
        __syncthreads();
        sm[threadIdx.x] += t;
        __syncthreads();
    }
    if (gid < NN) rp[gid] = sm[threadIdx.x] - v;   // exclusive
    if (threadIdx.x == SCAN_B - 1) bsum[blockIdx.x] = sm[SCAN_B - 1];
}

__global__ void __launch_bounds__(SCAN_B) scanC_kernel(int* __restrict__ rp,
                                                       const int* __restrict__ bsum,
                                                       int* __restrict__ cursor) {
    __shared__ int sb[128];
    int tid = threadIdx.x;
    if (tid < 128) sb[tid] = (tid < (int)blockIdx.x && tid < NBLK) ? bsum[tid] : 0;
    __syncthreads();
#pragma unroll
    for (int s = 64; s > 0; s >>= 1) {
        if (tid < s) sb[tid] += sb[tid + s];
        __syncthreads();
    }
    int off = sb[0];
    int gid = blockIdx.x * SCAN_B + tid;
    if (gid < NN) {
        int v = rp[gid] + off;
        rp[gid] = v;
        cursor[gid] = v;
    }
    if (gid == 0) rp[NN] = EE;
}

__global__ void __launch_bounds__(256) fill_kernel(const int* __restrict__ ei,
                                                   int* __restrict__ cursor,
                                                   int* __restrict__ csr) {
    int e4 = blockIdx.x * 256 + threadIdx.x;
    if (e4 < EE / 4) {
        int4 s = ((const int4*)ei)[e4];
        int4 d = ((const int4*)(ei + EE))[e4];
        int p0 = atomicAdd(&cursor[d.x], 1); csr[p0] = s.x * DD;
        int p1 = atomicAdd(&cursor[d.y], 1); csr[p1] = s.y * DD;
        int p2 = atomicAdd(&cursor[d.z], 1); csr[p2] = s.z * DD;
        int p3 = atomicAdd(&cursor[d.w], 1); csr[p3] = s.w * DD;
    }
}

// ---------------------------------------------------------------------------
// convert x (fp32) -> u16 (fp16); pool exact x into pooled[0]
// ---------------------------------------------------------------------------
__global__ void __launch_bounds__(256) conv_kernel(
    const float* __restrict__ x, const int* __restrict__ batch,
    __half* __restrict__ u16, float* __restrict__ pooled0)
{
    int idx = blockIdx.x * 256 + threadIdx.x;
    int n = idx >> 4;
    int j = (idx & 15) << 2;
    float4 v = *(const float4*)(x + n * DD + j);
    sth4(u16 + n * DD + j, v);
    red4(pooled0 + batch[n] * DD + j, v);
}

// ---------------------------------------------------------------------------
// gather: z16[n] = (1+eps)*v16[n] + sum_nbr v16[nbr]
// 8 threads/node, LDG.128 feature loads, natural node order, unroll-4 body
// with fp16 pairwise-tree accumulation into fp32 master accumulators.
// csr entries are pre-scaled (src*DD). Exact grid: NN*8/256 = 3125 blocks.
// ---------------------------------------------------------------------------
__global__ void __launch_bounds__(256) gather8_kernel(
    const __half* __restrict__ v16,
    const int* __restrict__ rowptr, const int* __restrict__ csr,
    const float* __restrict__ eps_l, __half* __restrict__ z16)
{
    int idx = blockIdx.x * 256 + threadIdx.x;
    int n = idx >> 3;
    int j = (idx & 7) << 3;          // half offset within row
    int s = rowptr[n];
    int e = rowptr[n + 1];
    float em1 = 1.0f + *eps_l;
    const __half* vj = v16 + j;

    float a[8];
    {
        uint4 r = *(const uint4*)(vj + n * DD);
        float2 f0 = __half22float2(*(__half2*)&r.x);
        float2 f1 = __half22float2(*(__half2*)&r.y);
        float2 f2 = __half22float2(*(__half2*)&r.z);
        float2 f3 = __half22float2(*(__half2*)&r.w);
        a[0] = em1 * f0.x; a[1] = em1 * f0.y; a[2] = em1 * f1.x; a[3] = em1 * f1.y;
        a[4] = em1 * f2.x; a[5] = em1 * f2.y; a[6] = em1 * f3.x; a[7] = em1 * f3.y;
    }

    int i = s;
    for (; i + 4 <= e; i += 4) {
        int s0 = csr[i], s1 = csr[i + 1], s2 = csr[i + 2], s3 = csr[i + 3];
        uint4 r0 = *(const uint4*)(vj + s0);
        uint4 r1 = *(const uint4*)(vj + s1);
        uint4 r2 = *(const uint4*)(vj + s2);
        uint4 r3 = *(const uint4*)(vj + s3);
        acc8x4tree(a, r0, r1, r2, r3);
    }
    for (; i < e; i++) {
        uint4 r = *(const uint4*)(vj + csr[i]);
        acc8(a, r);
    }

    uint4 o;
    *(__half2*)&o.x = __floats2half2_rn(a[0], a[1]);
    *(__half2*)&o.y = __floats2half2_rn(a[2], a[3]);
    *(__half2*)&o.z = __floats2half2_rn(a[4], a[5]);
    *(__half2*)&o.w = __floats2half2_rn(a[6], a[7]);
    *(uint4*)(z16 + n * DD + j) = o;
}

// ---------------------------------------------------------------------------
// bnapply: u16 = relu(bn(u16)) in place (once per node) + pool into pooled_l
// ---------------------------------------------------------------------------
__global__ void __launch_bounds__(256) bnapply_kernel(
    __half* __restrict__ u16, const float* __restrict__ st,
    const float* __restrict__ gamma, const float* __restrict__ beta,
    const int* __restrict__ batch, float* __restrict__ pooled_l)
{
    __shared__ float ab_s[128];
    const int tid = threadIdx.x;
    if (tid < 64) {
        const float inv_n = 1.0f / (float)NN;
        float m = st[tid] * inv_n;
        float v = st[64 + tid] * inv_n - m * m;
        float rs = rsqrtf(v + BN_EPS);
        float al = gamma[tid] * rs;
        ab_s[tid] = al;
        ab_s[64 + tid] = beta[tid] - al * m;
    }
    __syncthreads();
    int idx = blockIdx.x * 256 + tid;
    int n = idx >> 4;
    int j = (idx & 15) << 2;
    float4 v = ldh4(u16 + n * DD + j);
    v = bnrelu4(v, ab_s[j + 0], ab_s[j + 1], ab_s[j + 2], ab_s[j + 3],
                ab_s[64 + j + 0], ab_s[64 + j + 1], ab_s[64 + j + 2], ab_s[64 + j + 3]);
    sth4(u16 + n * DD + j, v);
    red4(pooled_l + batch[n] * DD + j, v);
}

// ---------------------------------------------------------------------------
// Tensor-core GEMM: OutH[N,64] = T(A16)[N,64] @ W + bias  (fp16 out),
// fused column stats (fp32, computed pre-rounding).
// T = relu(alpha*x+beta) from st_in (null -> identity).
// ---------------------------------------------------------------------------
struct GemmSmem {
    __half Wh[64 * 72];                              // 9216 B, padded stride 72
    union {
        __half Ah[128 * 72];                         // 18432 B (stage)
        float  Ep[8 * 16 * 64];                      // 32768 B (epilogue)
    } u;
    float ab[128];
    float sst[128];
};

__global__ void __launch_bounds__(256) gemmh_kernel(
    const __half* __restrict__ A16, const float* __restrict__ Wf,
    const float* __restrict__ bias,
    const float* __restrict__ st_in, const float* __restrict__ gamma,
    const float* __restrict__ beta,
    __half* __restrict__ OutH, float* __restrict__ st_out, int nrows)
{
    __shared__ GemmSmem sm;
    const int tid = threadIdx.x;
    const int row0 = blockIdx.x * 128;

    if (tid < 128) sm.sst[tid] = 0.f;
    if (st_in && tid < 64) {
        const float inv_n = 1.0f / (float)NN;
        float m = st_in[tid] * inv_n;
        float v = st_in[64 + tid] * inv_n - m * m;
        float rs = rsqrtf(v + BN_EPS);
        float al = gamma[tid] * rs;
        sm.ab[tid] = al;
        sm.ab[64 + tid] = beta[tid] - al * m;
    }
    // W (fp32 global) -> fp16 smem, stride 72
    for (int i = tid; i < 1024; i += 256) {
        int k = i >> 4, c = (i & 15) << 2;
        float4 w = *(const float4*)(Wf + k * 64 + c);
        uint2 p;
        *(__half2*)&p.x = __floats2half2_rn(w.x, w.y);
        *(__half2*)&p.y = __floats2half2_rn(w.z, w.w);
        *(uint2*)&sm.Wh[k * 72 + c] = p;
    }
    __syncthreads();   // ab ready before staging uses it

    // stage A (fp16 global) -> fp16 smem with optional BN+ReLU
    if (st_in) {
        for (int i = tid; i < 2048; i += 256) {
            int r = i >> 4, c = (i & 15) << 2;
            int gr = row0 + r;
            float4 a = make_float4(0.f, 0.f, 0.f, 0.f);
            if (gr < nrows) {
                a = ldh4(A16 + gr * 64 + c);
                a = bnrelu4(a, sm.ab[c + 0], sm.ab[c + 1], sm.ab[c + 2], sm.ab[c + 3],
                            sm.ab[64 + c + 0], sm.ab[64 + c + 1],
                            sm.ab[64 + c + 2], sm.ab[64 + c + 3]);
            }
            sth4(&sm.u.Ah[r * 72 + c], a);
        }
    } else {
        for (int i = tid; i < 2048; i += 256) {
            int r = i >> 4, c = (i & 15) << 2;
            int gr = row0 + r;
            uint2 val = make_uint2(0u, 0u);
            if (gr < nrows) val = *(const uint2*)(A16 + gr * 64 + c);
            *(uint2*)&sm.u.Ah[r * 72 + c] = val;
        }
    }
    __syncthreads();

    // -------- tensor-core mainloop --------
    const int w = tid >> 5;
    const int lane = tid & 31;

    wmma::fragment<wmma::accumulator, 16, 16, 16, float> cf[4];
#pragma unroll
    for (int n = 0; n < 4; n++) wmma::fill_fragment(cf[n], 0.f);

#pragma unroll
    for (int k = 0; k < 4; k++) {
        wmma::fragment<wmma::matrix_a, 16, 16, 16, __half, wmma::row_major> af;
        wmma::load_matrix_sync(af, &sm.u.Ah[(w * 16) * 72 + k * 16], 72);
#pragma unroll
        for (int n = 0; n < 4; n++) {
            wmma::fragment<wmma::matrix_b, 16, 16, 16, __half, wmma::row_major> bf;
            wmma::load_matrix_sync(bf, &sm.Wh[(k * 16) * 72 + n * 16], 72);
            wmma::mma_sync(cf[n], af, bf, cf[n]);
        }
    }
    __syncthreads();   // Ah no longer needed; Ep aliases it

    float* ep = sm.u.Ep + w * 1024;   // this warp's 16x64 tile
#pragma unroll
    for (int n = 0; n < 4; n++)
        wmma::store_matrix_sync(ep + n * 16, cf[n], 64, wmma::mem_row_major);
    __syncwarp();

    // -------- epilogue: bias, fp16 store, column stats --------
    const int c4 = (lane & 15) << 2;          // fixed column group per lane
    float4 b4 = *(const float4*)(bias + c4);
    float4 s = make_float4(0.f, 0.f, 0.f, 0.f), q = s;
#pragma unroll
    for (int jj = 0; jj < 8; jj++) {
        int r = (lane >> 4) + 2 * jj;         // 0..15
        int gr = row0 + w * 16 + r;
        if (gr < nrows) {
            float4 v = *(const float4*)(ep + r * 64 + c4);
            v.x += b4.x; v.y += b4.y; v.z += b4.z; v.w += b4.w;
            sth4(OutH + gr * 64 + c4, v);
            s.x += v.x; s.y += v.y; s.z += v.z; s.w += v.w;
            q.x += v.x * v.x; q.y += v.y * v.y; q.z += v.z * v.z; q.w += v.w * v.w;
        }
    }
    // lanes l and l+16 share the column group
    s.x += __shfl_xor_sync(~0u, s.x, 16); s.y += __shfl_xor_sync(~0u, s.y, 16);
    s.z += __shfl_xor_sync(~0u, s.z, 16); s.w += __shfl_xor_sync(~0u, s.w, 16);
    q.x += __shfl_xor_sync(~0u, q.x, 16); q.y += __shfl_xor_sync(~0u, q.y, 16);
    q.z += __shfl_xor_sync(~0u, q.z, 16); q.w += __shfl_xor_sync(~0u, q.w, 16);
    if (lane < 16) {
        atomicAdd(&sm.sst[c4 + 0], s.x); atomicAdd(&sm.sst[c4 + 1], s.y);
        atomicAdd(&sm.sst[c4 + 2], s.z); atomicAdd(&sm.sst[c4 + 3], s.w);
        atomicAdd(&sm.sst[64 + c4 + 0], q.x); atomicAdd(&sm.sst[64 + c4 + 1], q.y);
        atomicAdd(&sm.sst[64 + c4 + 2], q.z); atomicAdd(&sm.sst[64 + c4 + 3], q.w);
    }
    __syncthreads();
    if (tid < 128) atomicAdd(&st_out[tid], sm.sst[tid]);
}

// ---------------------------------------------------------------------------
// final readout
// ---------------------------------------------------------------------------
__global__ void score_kernel(const float* __restrict__ pooled,
                             const float* __restrict__ Wp,
                             const float* __restrict__ bp,
                             float* __restrict__ out)
{
    int t = blockIdx.x * 256 + threadIdx.x;
    if (t >= GG * CC) return;
    int g = t / CC, c = t % CC;
    float acc = 0.f;
#pragma unroll
    for (int l = 0; l < LL; l++) {
        acc += bp[l * CC + c];
        const float* pl = pooled + (l * GG + g) * DD;
        const float* wl = Wp + l * DD * CC + c;
        float s = 0.f;
#pragma unroll
        for (int d = 0; d < DD; d++) s += pl[d] * wl[d * CC];
        acc += s;
    }
    out[g * CC + c] = acc;
}

// ---------------------------------------------------------------------------
extern "C" void kernel_launch(void* const* d_in, const int* in_sizes, int n_in,
                              void* d_out, int out_size)
{
    (void)in_sizes; (void)n_in; (void)out_size;
    const float* x     = (const float*)d_in[0];
    const int*   ei    = (const int*)d_in[1];
    const int*   batch = (const int*)d_in[2];
    const float* eps   = (const float*)d_in[3];
    const float* W1    = (const float*)d_in[4];
    const float* b1    = (const float*)d_in[5];
    const float* g1    = (const float*)d_in[6];
    const float* be1   = (const float*)d_in[7];
    const float* W2    = (const float*)d_in[8];
    const float* b2    = (const float*)d_in[9];
    const float* gout  = (const float*)d_in[10];
    const float* beout = (const float*)d_in[11];
    const float* Wp    = (const float*)d_in[12];
    const float* bp    = (const float*)d_in[13];

    __half *u16, *z16, *t16;
    float *pooled, *stats;
    int *rowptr, *cursor, *csr, *bsum;
    cudaGetSymbolAddress((void**)&u16, g_u16);
    cudaGetSymbolAddress((void**)&z16, g_z16);
    cudaGetSymbolAddress((void**)&t16, g_t16);
    cudaGetSymbolAddress((void**)&pooled, g_pooled);
    cudaGetSymbolAddress((void**)&stats, g_stats);
    cudaGetSymbolAddress((void**)&rowptr, g_rowptr);
    cudaGetSymbolAddress((void**)&cursor, g_cursor);
    cudaGetSymbolAddress((void**)&csr, g_csr);
    cudaGetSymbolAddress((void**)&bsum, g_bsum);

    const int HPB  = (NN * 16) / 256;         // 6250 (exact, 16 thr/node kernels)
    const int HPB8 = (NN * 8) / 256;          // 3125 (exact, 8 thr/node gather)
    const int EB4  = (EE / 4 + 255) / 256;    // 1563 (int4 edge kernels)
    const int GMB  = (NN + 127) / 128;        // 782

    zerok<<<(LL * GG * DD + 255) / 256, 256>>>(pooled, stats, rowptr);

    // CSR build
    hist_kernel<<<EB4, 256>>>(ei, rowptr);
    scanA_kernel<<<NBLK, SCAN_B>>>(rowptr, bsum);
    scanC_kernel<<<NBLK, SCAN_B>>>(rowptr, bsum, cursor);
    fill_kernel<<<EB4, 256>>>(ei, cursor, csr);

    // x -> fp16 (identity "transform"), pool hidden_rep[0] exactly
    conv_kernel<<<HPB, 256>>>(x, batch, u16, pooled);

    for (int l = 0; l < LL - 1; l++) {
        // u16 holds the transformed activation h_l (x for l=0)
        gather8_kernel<<<HPB8, 256>>>(u16, rowptr, csr, eps + l, z16);
        // GEMM1: t16 = z16 @ W1 + b1 (no input transform), stats -> 2l
        gemmh_kernel<<<GMB, 256>>>(z16, W1 + l * 4096, b1 + l * 64,
                                   nullptr, nullptr, nullptr,
                                   t16, stats + (2 * l) * 128, NN);
        // GEMM2: u16 = relu(bn(t16)) @ W2 + b2, stats -> 2l+1
        gemmh_kernel<<<GMB, 256>>>(t16, W2 + l * 4096, b2 + l * 64,
                                   stats + (2 * l) * 128, g1 + l * 64, be1 + l * 64,
                                   u16, stats + (2 * l + 1) * 128, NN);
        // h_{l+1} = relu(bn(u16)) in place + pool hidden_rep[l+1]
        bnapply_kernel<<<HPB, 256>>>(u16, stats + (2 * l + 1) * 128,
                                     gout + l * 64, beout + l * 64,
                                     batch, pooled + (l + 1) * GG * DD);
    }

    score_kernel<<<(GG * CC + 255) / 256, 256>>>(pooled, Wp, bp, (float*)d_out);
}